// round 9
// baseline (speedup 1.0000x reference)
#include <cuda_runtime.h>
#include <cuda_fp16.h>
#include <math.h>
#include <stdint.h>

#define MAX_N 50000
#define MAX_E 800000
#define D 128
#define C 40
#define NB 64

// ---------------- static scratch ----------------
__device__ int   g_cnt[MAX_N];
__device__ int   g_degc[MAX_N];
__device__ int   g_rowptr[MAX_N + 1];
__device__ int   g_off[MAX_N];
__device__ int   g_bsum[NB];
__device__ int   g_boff[NB];
__device__ int   g_csrc[MAX_E];
__device__ float g_csw[MAX_E];
__device__ float g_dinv[MAX_N];
// fp16 feature buffers (uint4 for 16B alignment)
__device__ uint4 g_x16_[MAX_N * D / 8];
__device__ uint4 g_tx1h_[MAX_N * D / 8];
__device__ uint4 g_tx2h_[MAX_N * D / 8];
__device__ uint4 g_hh_[MAX_N * D / 8];
// layer-2 commuted intermediates: N x 40 fp16 each
__device__ uint4 g_p_[MAX_N * C / 8];    // Z0 - Z2
__device__ uint4 g_z1_[MAX_N * C / 8];
__device__ uint4 g_z2_[MAX_N * C / 8];
__device__ uint4 g_s1_[MAX_N * C / 8];   // L Z1
__device__ uint4 g_s2_[MAX_N * C / 8];   // L Z2
__device__ uint4 g_s3_[MAX_N * C / 8];   // L (L Z2)
// W2 concat-transposed fp16: [120n][128k], n = term*40 + class
__device__ uint4 g_w2tc_[120 * 128 / 8];

__device__ __forceinline__ uint32_t f2tf32(float f) {
    uint32_t u;
    asm("cvt.rna.tf32.f32 %0, %1;" : "=r"(u) : "f"(f));
    return u;
}

// ---------------- graph prep ----------------
__global__ void k_zero(int n) {
    int i = blockIdx.x * blockDim.x + threadIdx.x;
    if (i < n) { g_cnt[i] = 0; g_degc[i] = 0; }
}

__global__ void k_count(const int* __restrict__ ei, int E) {
    int e = blockIdx.x * blockDim.x + threadIdx.x;
    if (e < E) {
        atomicAdd(&g_degc[ei[e]], 1);
        atomicAdd(&g_cnt[ei[E + e]], 1);
    }
}

__global__ void k_dinv(int n) {
    int i = blockIdx.x * blockDim.x + threadIdx.x;
    if (i < n) {
        int d = g_degc[i];
        g_dinv[i] = (d > 0) ? rsqrtf((float)d) : 0.0f;
    }
}

__global__ void k_scan1(int n) {
    int b = blockIdx.x, t = threadIdx.x;
    int base = b * 1024 + t * 4;
    int s = 0;
#pragma unroll
    for (int j = 0; j < 4; ++j) {
        int i = base + j;
        if (i < n) s += g_cnt[i];
    }
#pragma unroll
    for (int o = 16; o; o >>= 1) s += __shfl_down_sync(0xffffffffu, s, o);
    __shared__ int ws[8];
    if ((t & 31) == 0) ws[t >> 5] = s;
    __syncthreads();
    if (t == 0) {
        int tot = 0;
#pragma unroll
        for (int w = 0; w < 8; ++w) tot += ws[w];
        g_bsum[b] = tot;
    }
}

__global__ void k_scan2(int nb, int n) {
    int t = threadIdx.x;
    int v0 = (2 * t < nb) ? g_bsum[2 * t] : 0;
    int v1 = (2 * t + 1 < nb) ? g_bsum[2 * t + 1] : 0;
    int s = v0 + v1;
    int inc = s;
#pragma unroll
    for (int o = 1; o < 32; o <<= 1) {
        int u = __shfl_up_sync(0xffffffffu, inc, o);
        if (t >= o) inc += u;
    }
    int exc = inc - s;
    if (2 * t < nb) g_boff[2 * t] = exc;
    if (2 * t + 1 < nb) g_boff[2 * t + 1] = exc + v0;
    if (t == 31) g_rowptr[n] = inc;
}

__global__ void k_scan3(int n) {
    int b = blockIdx.x, t = threadIdx.x;
    int base = b * 1024 + t * 4;
    int v[4];
    int s = 0;
#pragma unroll
    for (int j = 0; j < 4; ++j) {
        int i = base + j;
        v[j] = (i < n) ? g_cnt[i] : 0;
        s += v[j];
    }
    int inc = s;
#pragma unroll
    for (int o = 1; o < 32; o <<= 1) {
        int u = __shfl_up_sync(0xffffffffu, inc, o);
        if ((t & 31) >= o) inc += u;
    }
    __shared__ int ws[8];
    __shared__ int wo[8];
    if ((t & 31) == 31) ws[t >> 5] = inc;
    __syncthreads();
    if (t == 0) {
        int p = 0;
#pragma unroll
        for (int w = 0; w < 8; ++w) { wo[w] = p; p += ws[w]; }
    }
    __syncthreads();
    int pre = g_boff[b] + wo[t >> 5] + (inc - s);
#pragma unroll
    for (int j = 0; j < 4; ++j) {
        int i = base + j;
        if (i < n) { g_rowptr[i] = pre; g_off[i] = pre; }
        pre += v[j];
    }
}

__global__ void k_scatter(const int* __restrict__ ei, int E) {
    int e = blockIdx.x * blockDim.x + threadIdx.x;
    if (e < E) {
        int s = ei[e];
        int t = ei[E + e];
        int p = atomicAdd(&g_off[t], 1);
        g_csrc[p] = s;
        g_csw[p] = -g_dinv[s] * g_dinv[t];
    }
}

// ---------------- fp32 -> fp16 convert ----------------
__global__ void k_tohalf(const float* __restrict__ src, __half* __restrict__ dst, int n4) {
    int i = blockIdx.x * blockDim.x + threadIdx.x;
    if (i < n4) {
        float4 v = ((const float4*)src)[i];
        __half2 h0 = __floats2half2_rn(v.x, v.y);
        __half2 h1 = __floats2half2_rn(v.z, v.w);
        uint2 o;
        o.x = *(uint32_t*)&h0;
        o.y = *(uint32_t*)&h1;
        *(uint2*)(dst + (size_t)i * 4) = o;
    }
}

// W2 concat-transposed fp16: w2tc[term*40+cls][k] = W2[term][k][cls]
__global__ void k_w2tc(const float* __restrict__ W2) {
    int i = blockIdx.x * blockDim.x + threadIdx.x;   // 15360
    if (i < 120 * 128) {
        int nrow = i / 128;          // 0..119
        int k = i % 128;
        int term = nrow / C;
        int cls = nrow % C;
        ((__half*)g_w2tc_)[i] = __float2half(W2[(size_t)term * D * C + (size_t)k * C + cls]);
    }
}

// ---------------- SpMV: CSR gather, 2 edges/iter split-warp, 128-dim ----------------
__global__ void k_spmv_h(const __half* __restrict__ hin, __half* __restrict__ hout,
                         const __half* __restrict__ sub, float scale, int n) {
    int node = blockIdx.x * (blockDim.x >> 5) + (threadIdx.x >> 5);
    int lane = threadIdx.x & 31;
    int half = lane >> 4;
    int hl = lane & 15;
    if (node >= n) return;
    int beg = g_rowptr[node];
    int end = g_rowptr[node + 1];
    float acc[8];
#pragma unroll
    for (int q = 0; q < 8; ++q) acc[q] = 0.0f;

    for (int j = beg; j < end; j += 2) {
        int jj = j + half;
        if (jj < end) {
            int s = __ldg(&g_csrc[jj]);
            float w = __ldg(&g_csw[jj]);
            uint4 u = *(const uint4*)(hin + (size_t)s * D + hl * 8);
            float2 f0 = __half22float2(*(__half2*)&u.x);
            float2 f1 = __half22float2(*(__half2*)&u.y);
            float2 f2 = __half22float2(*(__half2*)&u.z);
            float2 f3 = __half22float2(*(__half2*)&u.w);
            acc[0] += w * f0.x; acc[1] += w * f0.y;
            acc[2] += w * f1.x; acc[3] += w * f1.y;
            acc[4] += w * f2.x; acc[5] += w * f2.y;
            acc[6] += w * f3.x; acc[7] += w * f3.y;
        }
    }
#pragma unroll
    for (int q = 0; q < 8; ++q)
        acc[q] += __shfl_xor_sync(0xffffffffu, acc[q], 16);

    if (half == 0) {
        float r[8];
        if (sub) {
            uint4 u = *(const uint4*)(sub + (size_t)node * D + hl * 8);
            float2 f0 = __half22float2(*(__half2*)&u.x);
            float2 f1 = __half22float2(*(__half2*)&u.y);
            float2 f2 = __half22float2(*(__half2*)&u.z);
            float2 f3 = __half22float2(*(__half2*)&u.w);
            r[0] = scale * acc[0] - f0.x; r[1] = scale * acc[1] - f0.y;
            r[2] = scale * acc[2] - f1.x; r[3] = scale * acc[3] - f1.y;
            r[4] = scale * acc[4] - f2.x; r[5] = scale * acc[5] - f2.y;
            r[6] = scale * acc[6] - f3.x; r[7] = scale * acc[7] - f3.y;
        } else {
#pragma unroll
            for (int q = 0; q < 8; ++q) r[q] = acc[q];
        }
        __half2 h0 = __floats2half2_rn(r[0], r[1]);
        __half2 h1 = __floats2half2_rn(r[2], r[3]);
        __half2 h2 = __floats2half2_rn(r[4], r[5]);
        __half2 h3 = __floats2half2_rn(r[6], r[7]);
        uint4 o;
        o.x = *(uint32_t*)&h0; o.y = *(uint32_t*)&h1;
        o.z = *(uint32_t*)&h2; o.w = *(uint32_t*)&h3;
        *(uint4*)(hout + (size_t)node * D + hl * 8) = o;
    }
}

// ---------------- SpMV: 40-dim rows (layer-2 commuted path) ----------------
// 2 edges/iter split-warp: half = lane>>4, hl = lane&15; hl<10 active, 4 halves each.
__global__ void k_spmv40(const __half* __restrict__ hin, __half* __restrict__ hout,
                         float scale, int n) {
    int node = blockIdx.x * (blockDim.x >> 5) + (threadIdx.x >> 5);
    int lane = threadIdx.x & 31;
    int half = lane >> 4;
    int hl = lane & 15;
    if (node >= n) return;
    int beg = g_rowptr[node];
    int end = g_rowptr[node + 1];
    float acc[4] = {0.f, 0.f, 0.f, 0.f};
    bool act = hl < 10;

    for (int j = beg; j < end; j += 2) {
        int jj = j + half;
        if (jj < end && act) {
            int s = __ldg(&g_csrc[jj]);
            float w = __ldg(&g_csw[jj]);
            uint2 u = *(const uint2*)(hin + (size_t)s * C + hl * 4);
            float2 f0 = __half22float2(*(__half2*)&u.x);
            float2 f1 = __half22float2(*(__half2*)&u.y);
            acc[0] += w * f0.x; acc[1] += w * f0.y;
            acc[2] += w * f1.x; acc[3] += w * f1.y;
        }
    }
#pragma unroll
    for (int q = 0; q < 4; ++q)
        acc[q] += __shfl_xor_sync(0xffffffffu, acc[q], 16);

    if (half == 0 && act) {
        __half2 h0 = __floats2half2_rn(scale * acc[0], scale * acc[1]);
        __half2 h1 = __floats2half2_rn(scale * acc[2], scale * acc[3]);
        uint2 o;
        o.x = *(uint32_t*)&h0;
        o.y = *(uint32_t*)&h1;
        *(uint2*)(hout + (size_t)node * C + hl * 4) = o;
    }
}

// ---------------- layer-1 GEMM: tf32 tensor cores (R7-proven) ----------------
#define APAD 4
#define BPAD 8

__global__ void k_gemm1(const float* __restrict__ x, const float* __restrict__ W1,
                        const float* __restrict__ b1, int n) {
    __shared__ uint32_t As[128 * (32 + APAD)];
    __shared__ uint32_t Bs[32 * (128 + BPAD)];
    __shared__ float bsh[128];

    int tid = threadIdx.x;
    int wid = tid >> 5, lane = tid & 31;
    int wm = wid >> 1;
    int wn = wid & 1;
    int g = lane >> 2, tq = lane & 3;
    int row0 = blockIdx.x * 128;

    if (tid < 128) bsh[tid] = b1[tid];

    __half* hh = (__half*)g_hh_;

    float c[2][8][4];
#pragma unroll
    for (int mt = 0; mt < 2; ++mt)
#pragma unroll
        for (int nt = 0; nt < 8; ++nt)
#pragma unroll
            for (int q = 0; q < 4; ++q) c[mt][nt][q] = 0.0f;

    for (int ch = 0; ch < 12; ++ch) {
        int term = ch >> 2;
        int coff = (ch & 3) * 32;

#pragma unroll
        for (int q = 0; q < 4; ++q) {
            int idx = tid + q * 256;
            int r = idx >> 3;
            int c4 = (idx & 7) * 4;
            int grow = row0 + r;
            float4 v;
            if (term == 0) {
                v = (grow < n)
                    ? *(const float4*)(x + (size_t)grow * D + coff + c4)
                    : make_float4(0.f, 0.f, 0.f, 0.f);
            } else {
                const __half* A16 = (term == 1) ? (const __half*)g_tx1h_
                                                : (const __half*)g_tx2h_;
                if (grow < n) {
                    uint2 u = *(const uint2*)(A16 + (size_t)grow * D + coff + c4);
                    float2 f0 = __half22float2(*(__half2*)&u.x);
                    float2 f1 = __half22float2(*(__half2*)&u.y);
                    v = make_float4(f0.x, f0.y, f1.x, f1.y);
                } else {
                    v = make_float4(0.f, 0.f, 0.f, 0.f);
                }
            }
            uint32_t* p = &As[r * (32 + APAD) + c4];
            p[0] = f2tf32(v.x); p[1] = f2tf32(v.y);
            p[2] = f2tf32(v.z); p[3] = f2tf32(v.w);
        }
#pragma unroll
        for (int q = 0; q < 4; ++q) {
            int idx = tid + q * 256;
            int k = idx >> 5;
            int j4 = (idx & 31) * 4;
            float4 v = *(const float4*)(W1 + (size_t)term * D * D + (size_t)(coff + k) * D + j4);
            uint32_t* p = &Bs[k * (128 + BPAD) + j4];
            p[0] = f2tf32(v.x); p[1] = f2tf32(v.y);
            p[2] = f2tf32(v.z); p[3] = f2tf32(v.w);
        }
        __syncthreads();

#pragma unroll
        for (int ks = 0; ks < 4; ++ks) {
            int k0 = ks * 8;
            uint32_t a[2][4];
#pragma unroll
            for (int mt = 0; mt < 2; ++mt) {
                int r = wm * 32 + mt * 16 + g;
                const uint32_t* ar = &As[r * (32 + APAD)];
                a[mt][0] = ar[k0 + tq];
                a[mt][1] = ar[8 * (32 + APAD) + k0 + tq];
                a[mt][2] = ar[k0 + tq + 4];
                a[mt][3] = ar[8 * (32 + APAD) + k0 + tq + 4];
            }
#pragma unroll
            for (int nt = 0; nt < 8; ++nt) {
                int cc = wn * 64 + nt * 8 + g;
                uint32_t b0 = Bs[(k0 + tq) * (128 + BPAD) + cc];
                uint32_t b1r = Bs[(k0 + tq + 4) * (128 + BPAD) + cc];
#pragma unroll
                for (int mt = 0; mt < 2; ++mt) {
                    asm volatile(
                        "mma.sync.aligned.m16n8k8.row.col.f32.tf32.tf32.f32 "
                        "{%0,%1,%2,%3}, {%4,%5,%6,%7}, {%8,%9}, {%0,%1,%2,%3};\n"
                        : "+f"(c[mt][nt][0]), "+f"(c[mt][nt][1]),
                          "+f"(c[mt][nt][2]), "+f"(c[mt][nt][3])
                        : "r"(a[mt][0]), "r"(a[mt][1]), "r"(a[mt][2]), "r"(a[mt][3]),
                          "r"(b0), "r"(b1r));
                }
            }
        }
        __syncthreads();
    }

#pragma unroll
    for (int mt = 0; mt < 2; ++mt) {
#pragma unroll
        for (int nt = 0; nt < 8; ++nt) {
            int col = wn * 64 + nt * 8 + 2 * tq;
            float bb0 = bsh[col], bb1 = bsh[col + 1];
            int r0 = row0 + wm * 32 + mt * 16 + g;
            if (r0 < n) {
                __half2 v0 = __floats2half2_rn(fmaxf(c[mt][nt][0] + bb0, 0.f),
                                               fmaxf(c[mt][nt][1] + bb1, 0.f));
                *(__half2*)(hh + (size_t)r0 * D + col) = v0;
            }
            int r1 = r0 + 8;
            if (r1 < n) {
                __half2 v1 = __floats2half2_rn(fmaxf(c[mt][nt][2] + bb0, 0.f),
                                               fmaxf(c[mt][nt][3] + bb1, 0.f));
                *(__half2*)(hh + (size_t)r1 * D + col) = v1;
            }
        }
    }
}

// ---------------- layer-2 projection: Z = h @ [W0|W1|W2] (fp16 mma) ----------------
// Outputs: P = Z0 - Z2, Z1, Z2 (each N x 40 fp16). 256 thr / 8 warps x 16 rows.
// n = 120 -> 15 ntiles; K = 128 in 4 chunks of 32.
#define S2 40

__global__ void k_gemm2a(int n) {
    __shared__ __half As2[128 * S2];
    __shared__ __half Bs2[120 * S2];

    int tid = threadIdx.x;
    int wid = tid >> 5, lane = tid & 31;
    int g = lane >> 2, tq = lane & 3;
    int row0 = blockIdx.x * 128;

    const __half* hh = (const __half*)g_hh_;
    const __half* w2tc = (const __half*)g_w2tc_;
    __half* pb = (__half*)g_p_;
    __half* z1 = (__half*)g_z1_;
    __half* z2 = (__half*)g_z2_;

    float c[15][4];
#pragma unroll
    for (int nt = 0; nt < 15; ++nt)
#pragma unroll
        for (int q = 0; q < 4; ++q) c[nt][q] = 0.0f;

    for (int ch = 0; ch < 4; ++ch) {
        int coff = ch * 32;

        // A tile 128x32 halves: 512 uint4 / 256 thr
#pragma unroll
        for (int q = 0; q < 2; ++q) {
            int idx = tid + q * 256;
            int r = idx >> 2;
            int c8 = (idx & 3) * 8;
            int grow = row0 + r;
            uint4 v = (grow < n)
                ? *(const uint4*)(hh + (size_t)grow * D + coff + c8)
                : make_uint4(0u, 0u, 0u, 0u);
            *(uint4*)&As2[r * S2 + c8] = v;
        }
        // B tile 120n x 32k halves: 480 uint4 / 256 thr
#pragma unroll
        for (int q = 0; q < 2; ++q) {
            int idx = tid + q * 256;
            if (idx < 480) {
                int r = idx >> 2;
                int c8 = (idx & 3) * 8;
                *(uint4*)&Bs2[r * S2 + c8] =
                    *(const uint4*)(w2tc + (size_t)r * 128 + coff + c8);
            }
        }
        __syncthreads();

#pragma unroll
        for (int ks = 0; ks < 2; ++ks) {
            int kb = ks * 16;
            const __half* ar = &As2[(wid * 16 + g) * S2 + kb + 2 * tq];
            uint32_t a0 = *(const uint32_t*)ar;
            uint32_t a1 = *(const uint32_t*)(ar + 8 * S2);
            uint32_t a2 = *(const uint32_t*)(ar + 8);
            uint32_t a3 = *(const uint32_t*)(ar + 8 * S2 + 8);
#pragma unroll
            for (int nt = 0; nt < 15; ++nt) {
                const __half* br = &Bs2[(nt * 8 + g) * S2 + kb + 2 * tq];
                uint32_t b0 = *(const uint32_t*)br;
                uint32_t b1r = *(const uint32_t*)(br + 8);
                asm volatile(
                    "mma.sync.aligned.m16n8k16.row.col.f32.f16.f16.f32 "
                    "{%0,%1,%2,%3}, {%4,%5,%6,%7}, {%8,%9}, {%0,%1,%2,%3};\n"
                    : "+f"(c[nt][0]), "+f"(c[nt][1]), "+f"(c[nt][2]), "+f"(c[nt][3])
                    : "r"(a0), "r"(a1), "r"(a2), "r"(a3), "r"(b0), "r"(b1r));
            }
        }
        __syncthreads();
    }

    // epilogue: P = Z0 - Z2 ; store Z1, Z2
    int r0 = row0 + wid * 16 + g;
    int r1 = r0 + 8;
#pragma unroll
    for (int nt5 = 0; nt5 < 5; ++nt5) {
        int col = nt5 * 8 + 2 * tq;
        // row r0 (frag idx 0,1); row r1 (frag idx 2,3)
        if (r0 < n) {
            __half2 hp = __floats2half2_rn(c[nt5][0] - c[10 + nt5][0],
                                           c[nt5][1] - c[10 + nt5][1]);
            __half2 h1 = __floats2half2_rn(c[5 + nt5][0], c[5 + nt5][1]);
            __half2 h2 = __floats2half2_rn(c[10 + nt5][0], c[10 + nt5][1]);
            *(__half2*)(pb + (size_t)r0 * C + col) = hp;
            *(__half2*)(z1 + (size_t)r0 * C + col) = h1;
            *(__half2*)(z2 + (size_t)r0 * C + col) = h2;
        }
        if (r1 < n) {
            __half2 hp = __floats2half2_rn(c[nt5][2] - c[10 + nt5][2],
                                           c[nt5][3] - c[10 + nt5][3]);
            __half2 h1 = __floats2half2_rn(c[5 + nt5][2], c[5 + nt5][3]);
            __half2 h2 = __floats2half2_rn(c[10 + nt5][2], c[10 + nt5][3]);
            *(__half2*)(pb + (size_t)r1 * C + col) = hp;
            *(__half2*)(z1 + (size_t)r1 * C + col) = h1;
            *(__half2*)(z2 + (size_t)r1 * C + col) = h2;
        }
    }
}

// ---------------- final combine + log_softmax ----------------
// out[i] = logsoftmax(P[i] + S1[i] + 2*S3[i] + b2). One warp per row; lanes 0-19.
__global__ void k_final(const float* __restrict__ b2, float* __restrict__ out, int n) {
    int w = (blockIdx.x * blockDim.x + threadIdx.x) >> 5;
    int lane = threadIdx.x & 31;
    if (w >= n) return;
    const __half* pb = (const __half*)g_p_;
    const __half* s1 = (const __half*)g_s1_;
    const __half* s3 = (const __half*)g_s3_;

    bool act = lane < 20;
    float a0 = -INFINITY, a1 = -INFINITY;
    if (act) {
        int base = w * C + 2 * lane;
        float2 fp = __half22float2(*(const __half2*)(pb + base));
        float2 f1 = __half22float2(*(const __half2*)(s1 + base));
        float2 f3 = __half22float2(*(const __half2*)(s3 + base));
        a0 = fp.x + f1.x + 2.0f * f3.x + b2[2 * lane];
        a1 = fp.y + f1.y + 2.0f * f3.y + b2[2 * lane + 1];
    }
    float m = fmaxf(a0, a1);
#pragma unroll
    for (int o = 16; o; o >>= 1) m = fmaxf(m, __shfl_xor_sync(0xffffffffu, m, o));
    float s = act ? (__expf(a0 - m) + __expf(a1 - m)) : 0.0f;
#pragma unroll
    for (int o = 16; o; o >>= 1) s += __shfl_xor_sync(0xffffffffu, s, o);
    float lse = m + logf(s);
    if (act)
        *(float2*)(out + (size_t)w * C + 2 * lane) = make_float2(a0 - lse, a1 - lse);
}

static void* sym_addr(const void* sym) {
    void* p = nullptr;
    cudaGetSymbolAddress(&p, sym);
    return p;
}

extern "C" void kernel_launch(void* const* d_in, const int* in_sizes, int n_in,
                              void* d_out, int out_size) {
    const float* x  = (const float*)d_in[0];
    const int*   ei = (const int*)d_in[1];
    const float* W1 = (const float*)d_in[2];
    const float* b1 = (const float*)d_in[3];
    const float* W2 = (const float*)d_in[4];
    const float* b2 = (const float*)d_in[5];
    float*       out = (float*)d_out;

    int N = in_sizes[0] / D;
    int E = in_sizes[1] / 2;
    int n4 = N * D / 4;

    __half* x16  = (__half*)sym_addr((const void*)g_x16_);
    __half* tx1h = (__half*)sym_addr((const void*)g_tx1h_);
    __half* tx2h = (__half*)sym_addr((const void*)g_tx2h_);
    __half* z1   = (__half*)sym_addr((const void*)g_z1_);
    __half* z2   = (__half*)sym_addr((const void*)g_z2_);
    __half* s1   = (__half*)sym_addr((const void*)g_s1_);
    __half* s2   = (__half*)sym_addr((const void*)g_s2_);
    __half* s3   = (__half*)sym_addr((const void*)g_s3_);

    dim3 b256(256);
    int gN  = (N + 255) / 256;
    int gE  = (E + 255) / 256;
    int gN4 = (n4 + 255) / 256;
    int gSp = (N * 32 + 255) / 256;
    int gG  = (N + 127) / 128;
    int nb  = (N + 1023) / 1024;

    // graph prep + weight conversion
    k_zero<<<gN, b256>>>(N);
    k_count<<<gE, b256>>>(ei, E);
    k_dinv<<<gN, b256>>>(N);
    k_scan1<<<nb, b256>>>(N);
    k_scan2<<<1, 32>>>(nb, N);
    k_scan3<<<nb, b256>>>(N);
    k_scatter<<<gE, b256>>>(ei, E);
    k_w2tc<<<(120 * 128 + 255) / 256, b256>>>(W2);

    // layer 1: Tx1 = L~ x ; Tx2 = 2 L~ Tx1 - x ; h = relu([x|Tx1|Tx2] W1 + b1)
    k_tohalf<<<gN4, b256>>>(x, x16, n4);
    k_spmv_h<<<gSp, b256>>>(x16,  tx1h, nullptr, 1.0f, N);
    k_spmv_h<<<gSp, b256>>>(tx1h, tx2h, x16,     2.0f, N);
    k_gemm1<<<gG, b256>>>(x, W1, b1, N);

    // layer 2 (commuted): Z = h W2cat ; out = (Z0 - Z2) + L~Z1 + 2 L~(L~Z2) + b2
    k_gemm2a<<<gG, b256>>>(N);
    k_spmv40<<<gSp, b256>>>(z1, s1, 1.0f, N);
    k_spmv40<<<gSp, b256>>>(z2, s2, 1.0f, N);
    k_spmv40<<<gSp, b256>>>(s2, s3, 1.0f, N);
    k_final<<<gSp, b256>>>(b2, out, N);
}

// round 10
// speedup vs baseline: 1.0756x; 1.0756x over previous
#include <cuda_runtime.h>
#include <cuda_fp16.h>
#include <math.h>
#include <stdint.h>

#define MAX_N 50000
#define MAX_E 800000
#define D 128
#define C 40
#define NB 64

// ---------------- static scratch ----------------
__device__ int   g_cnt[MAX_N];
__device__ int   g_degc[MAX_N];
__device__ int   g_rowptr[MAX_N + 1];
__device__ int   g_off[MAX_N];
__device__ int   g_bagg[NB];
__device__ int   g_bflag[NB];
__device__ int   g_csrc[MAX_E];
__device__ float g_csw[MAX_E];
__device__ float g_dinv[MAX_N];
// fp16 feature buffers (uint4 for 16B alignment)
__device__ uint4 g_x16_[MAX_N * D / 8];
__device__ uint4 g_tx1h_[MAX_N * D / 8];
__device__ uint4 g_tx2h_[MAX_N * D / 8];
__device__ uint4 g_hh_[MAX_N * D / 8];
// W2^T fp16: [40][384] (term-major k)
__device__ uint4 g_w2t_[40 * 384 / 8];

__device__ __forceinline__ uint32_t f2tf32(float f) {
    uint32_t u;
    asm("cvt.rna.tf32.f32 %0, %1;" : "=r"(u) : "f"(f));
    return u;
}

// ---------------- graph prep ----------------
__global__ void k_zero(int n) {
    int i = blockIdx.x * blockDim.x + threadIdx.x;
    if (i < n) { g_cnt[i] = 0; g_degc[i] = 0; }
    if (i < NB) { g_bflag[i] = 0; g_bagg[i] = 0; }
}

__global__ void k_count(const int* __restrict__ ei, int E) {
    int e = blockIdx.x * blockDim.x + threadIdx.x;
    if (e < E) {
        atomicAdd(&g_degc[ei[e]], 1);
        atomicAdd(&g_cnt[ei[E + e]], 1);
    }
}

// fused: dinv (grid-stride) + single-pass scan with parallel predecessor wait.
// grid = nb (<=49) blocks of 256; all blocks co-resident (148 SMs) -> no deadlock.
__global__ void k_scanf(int n, int nb) {
    int b = blockIdx.x, t = threadIdx.x;

    // dinv over all nodes (grid-stride; independent of the scan below)
    for (int i = b * 256 + t; i < n; i += nb * 256) {
        int d = g_degc[i];
        g_dinv[i] = (d > 0) ? rsqrtf((float)d) : 0.0f;
    }

    // local chunk scan: chunk = b*1024 .. b*1024+1023, 4 elems/thread
    int base = b * 1024 + t * 4;
    int v[4];
    int s = 0;
#pragma unroll
    for (int j = 0; j < 4; ++j) {
        int i = base + j;
        v[j] = (i < n) ? g_cnt[i] : 0;
        s += v[j];
    }
    int inc = s;
#pragma unroll
    for (int o = 1; o < 32; o <<= 1) {
        int u = __shfl_up_sync(0xffffffffu, inc, o);
        if ((t & 31) >= o) inc += u;
    }
    __shared__ int ws[8];
    __shared__ int wo[8];
    __shared__ int stot;
    __shared__ int sbase;
    __shared__ int preds[NB];
    if ((t & 31) == 31) ws[t >> 5] = inc;
    __syncthreads();
    if (t == 0) {
        int p = 0;
#pragma unroll
        for (int w = 0; w < 8; ++w) { wo[w] = p; p += ws[w]; }
        stot = p;
        // publish this block's aggregate
        atomicExch(&g_bagg[b], p);
        __threadfence();
        atomicExch(&g_bflag[b], 1);
    }
    __syncthreads();

    // parallel wait: thread t (< b) waits on predecessor t
    if (t < b) {
        while (atomicAdd(&g_bflag[t], 0) == 0) { }
        preds[t] = atomicAdd(&g_bagg[t], 0);
    }
    __syncthreads();
    if (t == 0) {
        int acc = 0;
        for (int p = 0; p < b; ++p) acc += preds[p];
        sbase = acc;
        if (b == nb - 1) g_rowptr[n] = acc + stot;
    }
    __syncthreads();

    int pre = sbase + wo[t >> 5] + (inc - s);
#pragma unroll
    for (int j = 0; j < 4; ++j) {
        int i = base + j;
        if (i < n) { g_rowptr[i] = pre; g_off[i] = pre; }
        pre += v[j];
    }
}

__global__ void k_scatter(const int* __restrict__ ei, int E) {
    int e = blockIdx.x * blockDim.x + threadIdx.x;
    if (e < E) {
        int s = ei[e];
        int t = ei[E + e];
        int p = atomicAdd(&g_off[t], 1);
        g_csrc[p] = s;
        g_csw[p] = -g_dinv[s] * g_dinv[t];
    }
}

// ---------------- fused convert: x->fp16 AND W2^T->fp16 ----------------
__global__ void k_conv(const float* __restrict__ x, const float* __restrict__ W2, int n4) {
    int i = blockIdx.x * blockDim.x + threadIdx.x;
    if (i < n4) {
        float4 v = ((const float4*)x)[i];
        __half2 h0 = __floats2half2_rn(v.x, v.y);
        __half2 h1 = __floats2half2_rn(v.z, v.w);
        uint2 o;
        o.x = *(uint32_t*)&h0;
        o.y = *(uint32_t*)&h1;
        *(uint2*)((__half*)g_x16_ + (size_t)i * 4) = o;
    }
    if (i < C * 384) {
        int n = i / 384;
        int r = i % 384;
        int term = r >> 7;
        int k = r & 127;
        ((__half*)g_w2t_)[i] = __float2half(W2[(size_t)term * D * C + (size_t)k * C + n]);
    }
}

// ---------------- SpMV: CSR gather, 2 edges/iter split-warp (R7-proven) ----------------
__global__ void k_spmv_h(const __half* __restrict__ hin, __half* __restrict__ hout,
                         const __half* __restrict__ sub, float scale, int n) {
    int node = blockIdx.x * (blockDim.x >> 5) + (threadIdx.x >> 5);
    int lane = threadIdx.x & 31;
    int half = lane >> 4;
    int hl = lane & 15;
    if (node >= n) return;
    int beg = g_rowptr[node];
    int end = g_rowptr[node + 1];
    float acc[8];
#pragma unroll
    for (int q = 0; q < 8; ++q) acc[q] = 0.0f;

    for (int j = beg; j < end; j += 2) {
        int jj = j + half;
        if (jj < end) {
            int s = __ldg(&g_csrc[jj]);
            float w = __ldg(&g_csw[jj]);
            uint4 u = *(const uint4*)(hin + (size_t)s * D + hl * 8);
            float2 f0 = __half22float2(*(__half2*)&u.x);
            float2 f1 = __half22float2(*(__half2*)&u.y);
            float2 f2 = __half22float2(*(__half2*)&u.z);
            float2 f3 = __half22float2(*(__half2*)&u.w);
            acc[0] += w * f0.x; acc[1] += w * f0.y;
            acc[2] += w * f1.x; acc[3] += w * f1.y;
            acc[4] += w * f2.x; acc[5] += w * f2.y;
            acc[6] += w * f3.x; acc[7] += w * f3.y;
        }
    }
#pragma unroll
    for (int q = 0; q < 8; ++q)
        acc[q] += __shfl_xor_sync(0xffffffffu, acc[q], 16);

    if (half == 0) {
        float r[8];
        if (sub) {
            uint4 u = *(const uint4*)(sub + (size_t)node * D + hl * 8);
            float2 f0 = __half22float2(*(__half2*)&u.x);
            float2 f1 = __half22float2(*(__half2*)&u.y);
            float2 f2 = __half22float2(*(__half2*)&u.z);
            float2 f3 = __half22float2(*(__half2*)&u.w);
            r[0] = scale * acc[0] - f0.x; r[1] = scale * acc[1] - f0.y;
            r[2] = scale * acc[2] - f1.x; r[3] = scale * acc[3] - f1.y;
            r[4] = scale * acc[4] - f2.x; r[5] = scale * acc[5] - f2.y;
            r[6] = scale * acc[6] - f3.x; r[7] = scale * acc[7] - f3.y;
        } else {
#pragma unroll
            for (int q = 0; q < 8; ++q) r[q] = acc[q];
        }
        __half2 h0 = __floats2half2_rn(r[0], r[1]);
        __half2 h1 = __floats2half2_rn(r[2], r[3]);
        __half2 h2 = __floats2half2_rn(r[4], r[5]);
        __half2 h3 = __floats2half2_rn(r[6], r[7]);
        uint4 o;
        o.x = *(uint32_t*)&h0; o.y = *(uint32_t*)&h1;
        o.z = *(uint32_t*)&h2; o.w = *(uint32_t*)&h3;
        *(uint4*)(hout + (size_t)node * D + hl * 8) = o;
    }
}

// ---------------- layer-1 GEMM: tf32 tensor cores (R7-proven) ----------------
#define APAD 4
#define BPAD 8

__global__ void k_gemm1(const float* __restrict__ x, const float* __restrict__ W1,
                        const float* __restrict__ b1, int n) {
    __shared__ uint32_t As[128 * (32 + APAD)];
    __shared__ uint32_t Bs[32 * (128 + BPAD)];
    __shared__ float bsh[128];

    int tid = threadIdx.x;
    int wid = tid >> 5, lane = tid & 31;
    int wm = wid >> 1;
    int wn = wid & 1;
    int g = lane >> 2, tq = lane & 3;
    int row0 = blockIdx.x * 128;

    if (tid < 128) bsh[tid] = b1[tid];

    __half* hh = (__half*)g_hh_;

    float c[2][8][4];
#pragma unroll
    for (int mt = 0; mt < 2; ++mt)
#pragma unroll
        for (int nt = 0; nt < 8; ++nt)
#pragma unroll
            for (int q = 0; q < 4; ++q) c[mt][nt][q] = 0.0f;

    for (int ch = 0; ch < 12; ++ch) {
        int term = ch >> 2;
        int coff = (ch & 3) * 32;

#pragma unroll
        for (int q = 0; q < 4; ++q) {
            int idx = tid + q * 256;
            int r = idx >> 3;
            int c4 = (idx & 7) * 4;
            int grow = row0 + r;
            float4 v;
            if (term == 0) {
                v = (grow < n)
                    ? *(const float4*)(x + (size_t)grow * D + coff + c4)
                    : make_float4(0.f, 0.f, 0.f, 0.f);
            } else {
                const __half* A16 = (term == 1) ? (const __half*)g_tx1h_
                                                : (const __half*)g_tx2h_;
                if (grow < n) {
                    uint2 u = *(const uint2*)(A16 + (size_t)grow * D + coff + c4);
                    float2 f0 = __half22float2(*(__half2*)&u.x);
                    float2 f1 = __half22float2(*(__half2*)&u.y);
                    v = make_float4(f0.x, f0.y, f1.x, f1.y);
                } else {
                    v = make_float4(0.f, 0.f, 0.f, 0.f);
                }
            }
            uint32_t* p = &As[r * (32 + APAD) + c4];
            p[0] = f2tf32(v.x); p[1] = f2tf32(v.y);
            p[2] = f2tf32(v.z); p[3] = f2tf32(v.w);
        }
#pragma unroll
        for (int q = 0; q < 4; ++q) {
            int idx = tid + q * 256;
            int k = idx >> 5;
            int j4 = (idx & 31) * 4;
            float4 v = *(const float4*)(W1 + (size_t)term * D * D + (size_t)(coff + k) * D + j4);
            uint32_t* p = &Bs[k * (128 + BPAD) + j4];
            p[0] = f2tf32(v.x); p[1] = f2tf32(v.y);
            p[2] = f2tf32(v.z); p[3] = f2tf32(v.w);
        }
        __syncthreads();

#pragma unroll
        for (int ks = 0; ks < 4; ++ks) {
            int k0 = ks * 8;
            uint32_t a[2][4];
#pragma unroll
            for (int mt = 0; mt < 2; ++mt) {
                int r = wm * 32 + mt * 16 + g;
                const uint32_t* ar = &As[r * (32 + APAD)];
                a[mt][0] = ar[k0 + tq];
                a[mt][1] = ar[8 * (32 + APAD) + k0 + tq];
                a[mt][2] = ar[k0 + tq + 4];
                a[mt][3] = ar[8 * (32 + APAD) + k0 + tq + 4];
            }
#pragma unroll
            for (int nt = 0; nt < 8; ++nt) {
                int cc = wn * 64 + nt * 8 + g;
                uint32_t b0 = Bs[(k0 + tq) * (128 + BPAD) + cc];
                uint32_t b1r = Bs[(k0 + tq + 4) * (128 + BPAD) + cc];
#pragma unroll
                for (int mt = 0; mt < 2; ++mt) {
                    asm volatile(
                        "mma.sync.aligned.m16n8k8.row.col.f32.tf32.tf32.f32 "
                        "{%0,%1,%2,%3}, {%4,%5,%6,%7}, {%8,%9}, {%0,%1,%2,%3};\n"
                        : "+f"(c[mt][nt][0]), "+f"(c[mt][nt][1]),
                          "+f"(c[mt][nt][2]), "+f"(c[mt][nt][3])
                        : "r"(a[mt][0]), "r"(a[mt][1]), "r"(a[mt][2]), "r"(a[mt][3]),
                          "r"(b0), "r"(b1r));
                }
            }
        }
        __syncthreads();
    }

#pragma unroll
    for (int mt = 0; mt < 2; ++mt) {
#pragma unroll
        for (int nt = 0; nt < 8; ++nt) {
            int col = wn * 64 + nt * 8 + 2 * tq;
            float bb0 = bsh[col], bb1 = bsh[col + 1];
            int r0 = row0 + wm * 32 + mt * 16 + g;
            if (r0 < n) {
                __half2 v0 = __floats2half2_rn(fmaxf(c[mt][nt][0] + bb0, 0.f),
                                               fmaxf(c[mt][nt][1] + bb1, 0.f));
                *(__half2*)(hh + (size_t)r0 * D + col) = v0;
            }
            int r1 = r0 + 8;
            if (r1 < n) {
                __half2 v1 = __floats2half2_rn(fmaxf(c[mt][nt][2] + bb0, 0.f),
                                               fmaxf(c[mt][nt][3] + bb1, 0.f));
                *(__half2*)(hh + (size_t)r1 * D + col) = v1;
            }
        }
    }
}

// ---------------- layer-2 GEMM: fp16 mma + fused log_softmax (R7-proven) ----------------
#define S2 40

__global__ void k_gemm2(const float* __restrict__ b2, float* __restrict__ out, int n) {
    __shared__ __half As2[128 * S2];
    __shared__ __half Bs2[40 * S2];
    __shared__ float bsh[40];

    int tid = threadIdx.x;
    int wid = tid >> 5, lane = tid & 31;
    int g = lane >> 2, tq = lane & 3;
    int row0 = blockIdx.x * 128;

    if (tid < 40) bsh[tid] = b2[tid];

    const __half* w2t = (const __half*)g_w2t_;

    float c[5][4];
#pragma unroll
    for (int nt = 0; nt < 5; ++nt)
#pragma unroll
        for (int q = 0; q < 4; ++q) c[nt][q] = 0.0f;

    for (int ch = 0; ch < 12; ++ch) {
        int term = ch >> 2;
        int coff = (ch & 3) * 32;
        const __half* A = (term == 0) ? (const __half*)g_hh_
                        : (term == 1) ? (const __half*)g_tx1h_
                                      : (const __half*)g_tx2h_;

#pragma unroll
        for (int q = 0; q < 2; ++q) {
            int idx = tid + q * 256;
            int r = idx >> 2;
            int c8 = (idx & 3) * 8;
            int grow = row0 + r;
            uint4 v = (grow < n)
                ? *(const uint4*)(A + (size_t)grow * D + coff + c8)
                : make_uint4(0u, 0u, 0u, 0u);
            *(uint4*)&As2[r * S2 + c8] = v;
        }
        if (tid < 160) {
            int r = tid >> 2;
            int c8 = (tid & 3) * 8;
            *(uint4*)&Bs2[r * S2 + c8] =
                *(const uint4*)(w2t + (size_t)r * 384 + term * 128 + coff + c8);
        }
        __syncthreads();

#pragma unroll
        for (int ks = 0; ks < 2; ++ks) {
            int kb = ks * 16;
            const __half* ar = &As2[(wid * 16 + g) * S2 + kb + 2 * tq];
            uint32_t a0 = *(const uint32_t*)ar;
            uint32_t a1 = *(const uint32_t*)(ar + 8 * S2);
            uint32_t a2 = *(const uint32_t*)(ar + 8);
            uint32_t a3 = *(const uint32_t*)(ar + 8 * S2 + 8);
#pragma unroll
            for (int nt = 0; nt < 5; ++nt) {
                const __half* br = &Bs2[(nt * 8 + g) * S2 + kb + 2 * tq];
                uint32_t b0 = *(const uint32_t*)br;
                uint32_t b1r = *(const uint32_t*)(br + 8);
                asm volatile(
                    "mma.sync.aligned.m16n8k16.row.col.f32.f16.f16.f32 "
                    "{%0,%1,%2,%3}, {%4,%5,%6,%7}, {%8,%9}, {%0,%1,%2,%3};\n"
                    : "+f"(c[nt][0]), "+f"(c[nt][1]), "+f"(c[nt][2]), "+f"(c[nt][3])
                    : "r"(a0), "r"(a1), "r"(a2), "r"(a3), "r"(b0), "r"(b1r));
            }
        }
        __syncthreads();
    }

    float zz[5][4];
#pragma unroll
    for (int nt = 0; nt < 5; ++nt) {
        float bb0 = bsh[nt * 8 + 2 * tq];
        float bb1 = bsh[nt * 8 + 2 * tq + 1];
        zz[nt][0] = c[nt][0] + bb0;
        zz[nt][1] = c[nt][1] + bb1;
        zz[nt][2] = c[nt][2] + bb0;
        zz[nt][3] = c[nt][3] + bb1;
    }
    float m0 = -INFINITY, m1 = -INFINITY;
#pragma unroll
    for (int nt = 0; nt < 5; ++nt) {
        m0 = fmaxf(m0, fmaxf(zz[nt][0], zz[nt][1]));
        m1 = fmaxf(m1, fmaxf(zz[nt][2], zz[nt][3]));
    }
    m0 = fmaxf(m0, __shfl_xor_sync(0xffffffffu, m0, 1));
    m0 = fmaxf(m0, __shfl_xor_sync(0xffffffffu, m0, 2));
    m1 = fmaxf(m1, __shfl_xor_sync(0xffffffffu, m1, 1));
    m1 = fmaxf(m1, __shfl_xor_sync(0xffffffffu, m1, 2));
    float s0 = 0.0f, s1 = 0.0f;
#pragma unroll
    for (int nt = 0; nt < 5; ++nt) {
        s0 += __expf(zz[nt][0] - m0) + __expf(zz[nt][1] - m0);
        s1 += __expf(zz[nt][2] - m1) + __expf(zz[nt][3] - m1);
    }
    s0 += __shfl_xor_sync(0xffffffffu, s0, 1);
    s0 += __shfl_xor_sync(0xffffffffu, s0, 2);
    s1 += __shfl_xor_sync(0xffffffffu, s1, 1);
    s1 += __shfl_xor_sync(0xffffffffu, s1, 2);
    float lse0 = m0 + logf(s0);
    float lse1 = m1 + logf(s1);

    int r0 = row0 + wid * 16 + g;
    int r1 = r0 + 8;
#pragma unroll
    for (int nt = 0; nt < 5; ++nt) {
        int col = nt * 8 + 2 * tq;
        if (r0 < n)
            *(float2*)(out + (size_t)r0 * C + col) =
                make_float2(zz[nt][0] - lse0, zz[nt][1] - lse0);
        if (r1 < n)
            *(float2*)(out + (size_t)r1 * C + col) =
                make_float2(zz[nt][2] - lse1, zz[nt][3] - lse1);
    }
}

static void* sym_addr(const void* sym) {
    void* p = nullptr;
    cudaGetSymbolAddress(&p, sym);
    return p;
}

extern "C" void kernel_launch(void* const* d_in, const int* in_sizes, int n_in,
                              void* d_out, int out_size) {
    const float* x  = (const float*)d_in[0];
    const int*   ei = (const int*)d_in[1];
    const float* W1 = (const float*)d_in[2];
    const float* b1 = (const float*)d_in[3];
    const float* W2 = (const float*)d_in[4];
    const float* b2 = (const float*)d_in[5];
    float*       out = (float*)d_out;

    int N = in_sizes[0] / D;
    int E = in_sizes[1] / 2;
    int n4 = N * D / 4;

    __half* x16  = (__half*)sym_addr((const void*)g_x16_);
    __half* tx1h = (__half*)sym_addr((const void*)g_tx1h_);
    __half* tx2h = (__half*)sym_addr((const void*)g_tx2h_);
    __half* hh   = (__half*)sym_addr((const void*)g_hh_);

    dim3 b256(256);
    int gN  = (N + 255) / 256;
    int gE  = (E + 255) / 256;
    int gN4 = (n4 + 255) / 256;
    int gSp = (N * 32 + 255) / 256;
    int gG  = (N + 127) / 128;
    int nb  = (N + 1023) / 1024;

    // graph prep: 5 launches (was 8)
    k_zero<<<gN, b256>>>(N);
    k_count<<<gE, b256>>>(ei, E);
    k_scanf<<<nb, b256>>>(N, nb);
    k_scatter<<<gE, b256>>>(ei, E);
    k_conv<<<gN4, b256>>>(x, W2, n4);

    // layer 1
    k_spmv_h<<<gSp, b256>>>(x16,  tx1h, nullptr, 1.0f, N);
    k_spmv_h<<<gSp, b256>>>(tx1h, tx2h, x16,     2.0f, N);
    k_gemm1<<<gG, b256>>>(x, W1, b1, N);

    // layer 2
    k_spmv_h<<<gSp, b256>>>(hh,   tx1h, nullptr, 1.0f, N);
    k_spmv_h<<<gSp, b256>>>(tx1h, tx2h, hh,      2.0f, N);
    k_gemm2<<<gG, b256>>>(b2, out, N);
}

// round 11
// speedup vs baseline: 1.1753x; 1.0926x over previous
#include <cuda_runtime.h>
#include <cuda_fp16.h>
#include <math.h>
#include <stdint.h>

#define MAX_N 50000
#define MAX_E 800000
#define D 128
#define C 40
#define NB 64

// ---------------- static scratch ----------------
__device__ int   g_cnt[MAX_N];
__device__ int   g_degc[MAX_N];
__device__ int   g_rowptr[MAX_N + 1];
__device__ int   g_off[MAX_N];
__device__ int   g_bagg[NB];
__device__ int   g_bflag[NB];
__device__ int   g_csrc[MAX_E];
__device__ float g_csw[MAX_E];
__device__ float g_dinv[MAX_N];
// fp16 feature buffers (uint4 for 16B alignment)
__device__ uint4 g_x16_[MAX_N * D / 8];
__device__ uint4 g_tx1h_[MAX_N * D / 8];
__device__ uint4 g_tx2h_[MAX_N * D / 8];
__device__ uint4 g_hh_[MAX_N * D / 8];
// W^T fp16: w1t [128n][384k], w2t [40n][384k]
__device__ uint4 g_w1t_[128 * 384 / 8];
__device__ uint4 g_w2t_[40 * 384 / 8];

// ---------------- graph prep ----------------
__global__ void k_zero(int n) {
    int i = blockIdx.x * blockDim.x + threadIdx.x;
    if (i < n) { g_cnt[i] = 0; g_degc[i] = 0; }
    if (i < NB) { g_bflag[i] = 0; g_bagg[i] = 0; }
}

__global__ void k_count(const int* __restrict__ ei, int E) {
    int e = blockIdx.x * blockDim.x + threadIdx.x;
    if (e < E) {
        atomicAdd(&g_degc[ei[e]], 1);
        atomicAdd(&g_cnt[ei[E + e]], 1);
    }
}

// fused: dinv (grid-stride) + single-pass scan with parallel predecessor wait.
__global__ void k_scanf(int n, int nb) {
    int b = blockIdx.x, t = threadIdx.x;

    for (int i = b * 256 + t; i < n; i += nb * 256) {
        int d = g_degc[i];
        g_dinv[i] = (d > 0) ? rsqrtf((float)d) : 0.0f;
    }

    int base = b * 1024 + t * 4;
    int v[4];
    int s = 0;
#pragma unroll
    for (int j = 0; j < 4; ++j) {
        int i = base + j;
        v[j] = (i < n) ? g_cnt[i] : 0;
        s += v[j];
    }
    int inc = s;
#pragma unroll
    for (int o = 1; o < 32; o <<= 1) {
        int u = __shfl_up_sync(0xffffffffu, inc, o);
        if ((t & 31) >= o) inc += u;
    }
    __shared__ int ws[8];
    __shared__ int wo[8];
    __shared__ int stot;
    __shared__ int sbase;
    __shared__ int preds[NB];
    if ((t & 31) == 31) ws[t >> 5] = inc;
    __syncthreads();
    if (t == 0) {
        int p = 0;
#pragma unroll
        for (int w = 0; w < 8; ++w) { wo[w] = p; p += ws[w]; }
        stot = p;
        atomicExch(&g_bagg[b], p);
        __threadfence();
        atomicExch(&g_bflag[b], 1);
    }
    __syncthreads();

    if (t < b) {
        while (atomicAdd(&g_bflag[t], 0) == 0) { }
        preds[t] = atomicAdd(&g_bagg[t], 0);
    }
    __syncthreads();
    if (t == 0) {
        int acc = 0;
        for (int p = 0; p < b; ++p) acc += preds[p];
        sbase = acc;
        if (b == nb - 1) g_rowptr[n] = acc + stot;
    }
    __syncthreads();

    int pre = sbase + wo[t >> 5] + (inc - s);
#pragma unroll
    for (int j = 0; j < 4; ++j) {
        int i = base + j;
        if (i < n) { g_rowptr[i] = pre; g_off[i] = pre; }
        pre += v[j];
    }
}

__global__ void k_scatter(const int* __restrict__ ei, int E) {
    int e = blockIdx.x * blockDim.x + threadIdx.x;
    if (e < E) {
        int s = ei[e];
        int t = ei[E + e];
        int p = atomicAdd(&g_off[t], 1);
        g_csrc[p] = s;
        g_csw[p] = -g_dinv[s] * g_dinv[t];
    }
}

// ---------------- fused convert: x->fp16, W1^T->fp16, W2^T->fp16 ----------------
__global__ void k_conv(const float* __restrict__ x, const float* __restrict__ W1,
                       const float* __restrict__ W2, int n4) {
    int i = blockIdx.x * blockDim.x + threadIdx.x;
    if (i < n4) {
        float4 v = ((const float4*)x)[i];
        __half2 h0 = __floats2half2_rn(v.x, v.y);
        __half2 h1 = __floats2half2_rn(v.z, v.w);
        uint2 o;
        o.x = *(uint32_t*)&h0;
        o.y = *(uint32_t*)&h1;
        *(uint2*)((__half*)g_x16_ + (size_t)i * 4) = o;
    }
    if (i < 128 * 384) {
        int n = i / 384;
        int r = i % 384;
        int term = r >> 7;
        int k = r & 127;
        ((__half*)g_w1t_)[i] = __float2half(W1[(size_t)term * D * D + (size_t)k * D + n]);
    }
    if (i < C * 384) {
        int n = i / 384;
        int r = i % 384;
        int term = r >> 7;
        int k = r & 127;
        ((__half*)g_w2t_)[i] = __float2half(W2[(size_t)term * D * C + (size_t)k * C + n]);
    }
}

// ---------------- SpMV: CSR gather, 2 edges/iter split-warp (R7/R10-proven) ----------------
__global__ void k_spmv_h(const __half* __restrict__ hin, __half* __restrict__ hout,
                         const __half* __restrict__ sub, float scale, int n) {
    int node = blockIdx.x * (blockDim.x >> 5) + (threadIdx.x >> 5);
    int lane = threadIdx.x & 31;
    int half = lane >> 4;
    int hl = lane & 15;
    if (node >= n) return;
    int beg = g_rowptr[node];
    int end = g_rowptr[node + 1];
    float acc[8];
#pragma unroll
    for (int q = 0; q < 8; ++q) acc[q] = 0.0f;

    for (int j = beg; j < end; j += 2) {
        int jj = j + half;
        if (jj < end) {
            int s = __ldg(&g_csrc[jj]);
            float w = __ldg(&g_csw[jj]);
            uint4 u = *(const uint4*)(hin + (size_t)s * D + hl * 8);
            float2 f0 = __half22float2(*(__half2*)&u.x);
            float2 f1 = __half22float2(*(__half2*)&u.y);
            float2 f2 = __half22float2(*(__half2*)&u.z);
            float2 f3 = __half22float2(*(__half2*)&u.w);
            acc[0] += w * f0.x; acc[1] += w * f0.y;
            acc[2] += w * f1.x; acc[3] += w * f1.y;
            acc[4] += w * f2.x; acc[5] += w * f2.y;
            acc[6] += w * f3.x; acc[7] += w * f3.y;
        }
    }
#pragma unroll
    for (int q = 0; q < 8; ++q)
        acc[q] += __shfl_xor_sync(0xffffffffu, acc[q], 16);

    if (half == 0) {
        float r[8];
        if (sub) {
            uint4 u = *(const uint4*)(sub + (size_t)node * D + hl * 8);
            float2 f0 = __half22float2(*(__half2*)&u.x);
            float2 f1 = __half22float2(*(__half2*)&u.y);
            float2 f2 = __half22float2(*(__half2*)&u.z);
            float2 f3 = __half22float2(*(__half2*)&u.w);
            r[0] = scale * acc[0] - f0.x; r[1] = scale * acc[1] - f0.y;
            r[2] = scale * acc[2] - f1.x; r[3] = scale * acc[3] - f1.y;
            r[4] = scale * acc[4] - f2.x; r[5] = scale * acc[5] - f2.y;
            r[6] = scale * acc[6] - f3.x; r[7] = scale * acc[7] - f3.y;
        } else {
#pragma unroll
            for (int q = 0; q < 8; ++q) r[q] = acc[q];
        }
        __half2 h0 = __floats2half2_rn(r[0], r[1]);
        __half2 h1 = __floats2half2_rn(r[2], r[3]);
        __half2 h2 = __floats2half2_rn(r[4], r[5]);
        __half2 h3 = __floats2half2_rn(r[6], r[7]);
        uint4 o;
        o.x = *(uint32_t*)&h0; o.y = *(uint32_t*)&h1;
        o.z = *(uint32_t*)&h2; o.w = *(uint32_t*)&h3;
        *(uint4*)(hout + (size_t)node * D + hl * 8) = o;
    }
}

// ---------------- layer-1 GEMM: fp16 mma (R8 kernel, unbundled test) ----------------
#define S1 40

__global__ void k_gemm1h(const float* __restrict__ b1, int n) {
    __shared__ __half As1[128 * S1];
    __shared__ __half Bs1[128 * S1];
    __shared__ float bsh[128];

    int tid = threadIdx.x;
    int wid = tid >> 5, lane = tid & 31;
    int wm = wid >> 1;
    int wn = wid & 1;
    int g = lane >> 2, tq = lane & 3;
    int row0 = blockIdx.x * 128;

    if (tid < 128) bsh[tid] = b1[tid];

    __half* hh = (__half*)g_hh_;
    const __half* w1t = (const __half*)g_w1t_;

    float c[2][8][4];
#pragma unroll
    for (int mt = 0; mt < 2; ++mt)
#pragma unroll
        for (int nt = 0; nt < 8; ++nt)
#pragma unroll
            for (int q = 0; q < 4; ++q) c[mt][nt][q] = 0.0f;

    for (int ch = 0; ch < 12; ++ch) {
        int term = ch >> 2;
        int coff = (ch & 3) * 32;
        const __half* A = (term == 0) ? (const __half*)g_x16_
                        : (term == 1) ? (const __half*)g_tx1h_
                                      : (const __half*)g_tx2h_;

#pragma unroll
        for (int q = 0; q < 2; ++q) {
            int idx = tid + q * 256;
            int r = idx >> 2;
            int c8 = (idx & 3) * 8;
            int grow = row0 + r;
            uint4 v = (grow < n)
                ? *(const uint4*)(A + (size_t)grow * D + coff + c8)
                : make_uint4(0u, 0u, 0u, 0u);
            *(uint4*)&As1[r * S1 + c8] = v;
        }
#pragma unroll
        for (int q = 0; q < 2; ++q) {
            int idx = tid + q * 256;
            int r = idx >> 2;
            int c8 = (idx & 3) * 8;
            *(uint4*)&Bs1[r * S1 + c8] =
                *(const uint4*)(w1t + (size_t)r * 384 + term * 128 + coff + c8);
        }
        __syncthreads();

#pragma unroll
        for (int ks = 0; ks < 2; ++ks) {
            int kb = ks * 16;
            uint32_t a[2][4];
#pragma unroll
            for (int mt = 0; mt < 2; ++mt) {
                const __half* ar = &As1[(wm * 32 + mt * 16 + g) * S1 + kb + 2 * tq];
                a[mt][0] = *(const uint32_t*)ar;
                a[mt][1] = *(const uint32_t*)(ar + 8 * S1);
                a[mt][2] = *(const uint32_t*)(ar + 8);
                a[mt][3] = *(const uint32_t*)(ar + 8 * S1 + 8);
            }
#pragma unroll
            for (int nt = 0; nt < 8; ++nt) {
                const __half* br = &Bs1[(wn * 64 + nt * 8 + g) * S1 + kb + 2 * tq];
                uint32_t b0 = *(const uint32_t*)br;
                uint32_t b1r = *(const uint32_t*)(br + 8);
#pragma unroll
                for (int mt = 0; mt < 2; ++mt) {
                    asm volatile(
                        "mma.sync.aligned.m16n8k16.row.col.f32.f16.f16.f32 "
                        "{%0,%1,%2,%3}, {%4,%5,%6,%7}, {%8,%9}, {%0,%1,%2,%3};\n"
                        : "+f"(c[mt][nt][0]), "+f"(c[mt][nt][1]),
                          "+f"(c[mt][nt][2]), "+f"(c[mt][nt][3])
                        : "r"(a[mt][0]), "r"(a[mt][1]), "r"(a[mt][2]), "r"(a[mt][3]),
                          "r"(b0), "r"(b1r));
                }
            }
        }
        __syncthreads();
    }

#pragma unroll
    for (int mt = 0; mt < 2; ++mt) {
#pragma unroll
        for (int nt = 0; nt < 8; ++nt) {
            int col = wn * 64 + nt * 8 + 2 * tq;
            float bb0 = bsh[col], bb1 = bsh[col + 1];
            int r0 = row0 + wm * 32 + mt * 16 + g;
            if (r0 < n) {
                __half2 v0 = __floats2half2_rn(fmaxf(c[mt][nt][0] + bb0, 0.f),
                                               fmaxf(c[mt][nt][1] + bb1, 0.f));
                *(__half2*)(hh + (size_t)r0 * D + col) = v0;
            }
            int r1 = r0 + 8;
            if (r1 < n) {
                __half2 v1 = __floats2half2_rn(fmaxf(c[mt][nt][2] + bb0, 0.f),
                                               fmaxf(c[mt][nt][3] + bb1, 0.f));
                *(__half2*)(hh + (size_t)r1 * D + col) = v1;
            }
        }
    }
}

// ---------------- layer-2 GEMM: fp16 mma + fused log_softmax (R7/R10-proven) ----------------
#define S2 40

__global__ void k_gemm2(const float* __restrict__ b2, float* __restrict__ out, int n) {
    __shared__ __half As2[128 * S2];
    __shared__ __half Bs2[40 * S2];
    __shared__ float bsh[40];

    int tid = threadIdx.x;
    int wid = tid >> 5, lane = tid & 31;
    int g = lane >> 2, tq = lane & 3;
    int row0 = blockIdx.x * 128;

    if (tid < 40) bsh[tid] = b2[tid];

    const __half* w2t = (const __half*)g_w2t_;

    float c[5][4];
#pragma unroll
    for (int nt = 0; nt < 5; ++nt)
#pragma unroll
        for (int q = 0; q < 4; ++q) c[nt][q] = 0.0f;

    for (int ch = 0; ch < 12; ++ch) {
        int term = ch >> 2;
        int coff = (ch & 3) * 32;
        const __half* A = (term == 0) ? (const __half*)g_hh_
                        : (term == 1) ? (const __half*)g_tx1h_
                                      : (const __half*)g_tx2h_;

#pragma unroll
        for (int q = 0; q < 2; ++q) {
            int idx = tid + q * 256;
            int r = idx >> 2;
            int c8 = (idx & 3) * 8;
            int grow = row0 + r;
            uint4 v = (grow < n)
                ? *(const uint4*)(A + (size_t)grow * D + coff + c8)
                : make_uint4(0u, 0u, 0u, 0u);
            *(uint4*)&As2[r * S2 + c8] = v;
        }
        if (tid < 160) {
            int r = tid >> 2;
            int c8 = (tid & 3) * 8;
            *(uint4*)&Bs2[r * S2 + c8] =
                *(const uint4*)(w2t + (size_t)r * 384 + term * 128 + coff + c8);
        }
        __syncthreads();

#pragma unroll
        for (int ks = 0; ks < 2; ++ks) {
            int kb = ks * 16;
            const __half* ar = &As2[(wid * 16 + g) * S2 + kb + 2 * tq];
            uint32_t a0 = *(const uint32_t*)ar;
            uint32_t a1 = *(const uint32_t*)(ar + 8 * S2);
            uint32_t a2 = *(const uint32_t*)(ar + 8);
            uint32_t a3 = *(const uint32_t*)(ar + 8 * S2 + 8);
#pragma unroll
            for (int nt = 0; nt < 5; ++nt) {
                const __half* br = &Bs2[(nt * 8 + g) * S2 + kb + 2 * tq];
                uint32_t b0 = *(const uint32_t*)br;
                uint32_t b1r = *(const uint32_t*)(br + 8);
                asm volatile(
                    "mma.sync.aligned.m16n8k16.row.col.f32.f16.f16.f32 "
                    "{%0,%1,%2,%3}, {%4,%5,%6,%7}, {%8,%9}, {%0,%1,%2,%3};\n"
                    : "+f"(c[nt][0]), "+f"(c[nt][1]), "+f"(c[nt][2]), "+f"(c[nt][3])
                    : "r"(a0), "r"(a1), "r"(a2), "r"(a3), "r"(b0), "r"(b1r));
            }
        }
        __syncthreads();
    }

    float zz[5][4];
#pragma unroll
    for (int nt = 0; nt < 5; ++nt) {
        float bb0 = bsh[nt * 8 + 2 * tq];
        float bb1 = bsh[nt * 8 + 2 * tq + 1];
        zz[nt][0] = c[nt][0] + bb0;
        zz[nt][1] = c[nt][1] + bb1;
        zz[nt][2] = c[nt][2] + bb0;
        zz[nt][3] = c[nt][3] + bb1;
    }
    float m0 = -INFINITY, m1 = -INFINITY;
#pragma unroll
    for (int nt = 0; nt < 5; ++nt) {
        m0 = fmaxf(m0, fmaxf(zz[nt][0], zz[nt][1]));
        m1 = fmaxf(m1, fmaxf(zz[nt][2], zz[nt][3]));
    }
    m0 = fmaxf(m0, __shfl_xor_sync(0xffffffffu, m0, 1));
    m0 = fmaxf(m0, __shfl_xor_sync(0xffffffffu, m0, 2));
    m1 = fmaxf(m1, __shfl_xor_sync(0xffffffffu, m1, 1));
    m1 = fmaxf(m1, __shfl_xor_sync(0xffffffffu, m1, 2));
    float s0 = 0.0f, s1 = 0.0f;
#pragma unroll
    for (int nt = 0; nt < 5; ++nt) {
        s0 += __expf(zz[nt][0] - m0) + __expf(zz[nt][1] - m0);
        s1 += __expf(zz[nt][2] - m1) + __expf(zz[nt][3] - m1);
    }
    s0 += __shfl_xor_sync(0xffffffffu, s0, 1);
    s0 += __shfl_xor_sync(0xffffffffu, s0, 2);
    s1 += __shfl_xor_sync(0xffffffffu, s1, 1);
    s1 += __shfl_xor_sync(0xffffffffu, s1, 2);
    float lse0 = m0 + logf(s0);
    float lse1 = m1 + logf(s1);

    int r0 = row0 + wid * 16 + g;
    int r1 = r0 + 8;
#pragma unroll
    for (int nt = 0; nt < 5; ++nt) {
        int col = nt * 8 + 2 * tq;
        if (r0 < n)
            *(float2*)(out + (size_t)r0 * C + col) =
                make_float2(zz[nt][0] - lse0, zz[nt][1] - lse0);
        if (r1 < n)
            *(float2*)(out + (size_t)r1 * C + col) =
                make_float2(zz[nt][2] - lse1, zz[nt][3] - lse1);
    }
}

static void* sym_addr(const void* sym) {
    void* p = nullptr;
    cudaGetSymbolAddress(&p, sym);
    return p;
}

extern "C" void kernel_launch(void* const* d_in, const int* in_sizes, int n_in,
                              void* d_out, int out_size) {
    const float* x  = (const float*)d_in[0];
    const int*   ei = (const int*)d_in[1];
    const float* W1 = (const float*)d_in[2];
    const float* b1 = (const float*)d_in[3];
    const float* W2 = (const float*)d_in[4];
    const float* b2 = (const float*)d_in[5];
    float*       out = (float*)d_out;

    int N = in_sizes[0] / D;
    int E = in_sizes[1] / 2;
    int n4 = N * D / 4;

    __half* x16  = (__half*)sym_addr((const void*)g_x16_);
    __half* tx1h = (__half*)sym_addr((const void*)g_tx1h_);
    __half* tx2h = (__half*)sym_addr((const void*)g_tx2h_);
    __half* hh   = (__half*)sym_addr((const void*)g_hh_);

    dim3 b256(256);
    int gN  = (N + 255) / 256;
    int gE  = (E + 255) / 256;
    int gN4 = (n4 + 255) / 256;
    int gSp = (N * 32 + 255) / 256;
    int gG  = (N + 127) / 128;
    int nb  = (N + 1023) / 1024;

    // graph prep: 5 launches
    k_zero<<<gN, b256>>>(N);
    k_count<<<gE, b256>>>(ei, E);
    k_scanf<<<nb, b256>>>(N, nb);
    k_scatter<<<gE, b256>>>(ei, E);
    k_conv<<<gN4, b256>>>(x, W1, W2, n4);

    // layer 1
    k_spmv_h<<<gSp, b256>>>(x16,  tx1h, nullptr, 1.0f, N);
    k_spmv_h<<<gSp, b256>>>(tx1h, tx2h, x16,     2.0f, N);
    k_gemm1h<<<gG, b256>>>(b1, N);

    // layer 2
    k_spmv_h<<<gSp, b256>>>(hh,   tx1h, nullptr, 1.0f, N);
    k_spmv_h<<<gSp, b256>>>(tx1h, tx2h, hh,      2.0f, N);
    k_gemm2<<<gG, b256>>>(b2, out, N);
}